// round 2
// baseline (speedup 1.0000x reference)
#include <cuda_runtime.h>
#include <cstdint>

// Problem constants
#define BB 32
#define LL 128
#define FF 128
#define RR 4096
#define NITEMS 262144
#define HALF (RR >> 1)

// out shape (B, R, F) = 32*4096*128 floats = 16,777,216

__device__ __forceinline__ void red4(float* p, float x, float y, float z, float w) {
    asm volatile("red.global.add.v4.f32 [%0], {%1, %2, %3, %4};"
                 :: "l"(p), "f"(x), "f"(y), "f"(z), "f"(w)
                 : "memory");
}

// Kernel 1: initialize output. Zero everywhere except (b, 1, f) = od2[b] * root[b, f].
__global__ void init_out_kernel(float4* __restrict__ out4,
                                const float* __restrict__ root,
                                const float* __restrict__ op_dist) {
    int64_t idx = (int64_t)blockIdx.x * blockDim.x + threadIdx.x;  // float4 index
    const int64_t total4 = (int64_t)BB * RR * FF / 4;              // 4,194,304
    if (idx >= total4) return;

    int64_t fidx = idx << 2;                 // float index
    int b = (int)(fidx / ((int64_t)RR * FF));
    int rem = (int)(fidx - (int64_t)b * RR * FF);
    int r = rem / FF;

    float4 v = make_float4(0.f, 0.f, 0.f, 0.f);
    if (r == 1) {
        int f = rem - r * FF;
        float od2 = op_dist[b * 3 + 2];
        float4 rf = *(const float4*)(root + (int64_t)b * FF + f);
        v = make_float4(od2 * rf.x, od2 * rf.y, od2 * rf.z, od2 * rf.w);
    }
    out4[idx] = v;
}

// Kernel 2: one warp per item. Each lane owns a float4 chunk (lane*4 .. lane*4+3)
// of the item's 128-float mem row, and performs up to 3 vectorized global
// reductions into the output rows this item feeds.
__global__ void __launch_bounds__(256) scatter_kernel(
    const float* __restrict__ mem,        // (N, F)
    const float* __restrict__ arg_w,      // (B, L, 4)
    const float* __restrict__ op_dist,    // (B, 3)
    const int*   __restrict__ batch_idx,  // (N,)
    const int*   __restrict__ slot_idx,   // (N,)
    const int*   __restrict__ role_idx,   // (N,)
    float* __restrict__ out)              // (B, R, F)
{
    const int warps_per_block = blockDim.x >> 5;
    int item = blockIdx.x * warps_per_block + (threadIdx.x >> 5);
    if (item >= NITEMS) return;
    const int lane = threadIdx.x & 31;

    // Load this lane's float4 of the mem row (coalesced 512B per warp).
    const float4 m = ((const float4*)(mem + (int64_t)item * FF))[lane];

    // Skip items whose entire mem row is zero (contributes nothing; also
    // makes the reference's `pad` masking a no-op numerically).
    bool nz = (m.x != 0.f) | (m.y != 0.f) | (m.z != 0.f) | (m.w != 0.f);
    if (!__any_sync(0xffffffffu, nz)) return;

    const int b    = batch_idx[item];
    const int slot = slot_idx[item];
    const int rho  = role_idx[item];

    // arg_weights[b, slot, 0:4] — one aligned 16B broadcast load.
    const float4 w = *(const float4*)(arg_w + (((int64_t)b * LL + slot) << 2));
    const float od0 = op_dist[b * 3 + 0];
    const float od1 = op_dist[b * 3 + 1];
    const float od2 = op_dist[b * 3 + 2];

    float* base = out + (int64_t)b * RR * FF + (lane << 2);

    // car / cdr destination (at most one of the two).
    if ((rho & 1) == 0) {
        // even role -> car: out[b, rho/2] += od0*w0*mem
        const float c = od0 * w.x;
        red4(base + (int64_t)(rho >> 1) * FF, c * m.x, c * m.y, c * m.z, c * m.w);
    } else if (rho != 1) {
        // odd role != 1 -> cdr: out[b, (rho-1)/2] += od1*w1*mem
        const float c = od1 * w.y;
        red4(base + (int64_t)(rho >> 1) * FF, c * m.x, c * m.y, c * m.z, c * m.w);
    }

    // cons destinations: only interior roles (rho < R/2).
    if (rho < HALF) {
        const float c1 = od2 * w.z;
        red4(base + (int64_t)(2 * rho) * FF, c1 * m.x, c1 * m.y, c1 * m.z, c1 * m.w);
        const float c2 = od2 * w.w;
        red4(base + (int64_t)(2 * rho + 1) * FF, c2 * m.x, c2 * m.y, c2 * m.z, c2 * m.w);
    }
}

extern "C" void kernel_launch(void* const* d_in, const int* in_sizes, int n_in,
                              void* d_out, int out_size) {
    const float* mem      = (const float*)d_in[0];  // (N, F) f32
    const float* arg_w    = (const float*)d_in[1];  // (B, L, 4) f32
    const float* root     = (const float*)d_in[2];  // (B, F) f32
    const float* op_dist  = (const float*)d_in[3];  // (B, 3) f32
    const int*   batch_i  = (const int*)d_in[4];    // (N,) i32
    const int*   slot_i   = (const int*)d_in[5];    // (N,) i32
    const int*   role_i   = (const int*)d_in[6];    // (N,) i32
    float* out = (float*)d_out;                     // (B, R, F) f32

    // 1) init output (zeros + od2*root at row r=1)
    {
        const int64_t total4 = (int64_t)BB * RR * FF / 4;
        const int threads = 256;
        const int blocks = (int)((total4 + threads - 1) / threads);
        init_out_kernel<<<blocks, threads>>>((float4*)out, root, op_dist);
    }

    // 2) scatter-add (one warp per item)
    {
        const int threads = 256;                 // 8 warps per block
        const int warps_per_block = threads / 32;
        const int blocks = (NITEMS + warps_per_block - 1) / warps_per_block;
        scatter_kernel<<<blocks, threads>>>(mem, arg_w, op_dist,
                                            batch_i, slot_i, role_i, out);
    }
}